// round 16
// baseline (speedup 1.0000x reference)
#include <cuda_runtime.h>
#include <cuda_fp16.h>
#include <cstdint>
#include <math.h>

#define T_SEQ 1024
#define EMB   1024
#define NH    16
#define HD    64
#define BATCH 8
#define NREL  2047
#define NSTG  3

// ---------------- scratch (device globals) ----------------------------------
__device__ __align__(16) float g_bias[NREL * NH];      // [h][rel]
__device__ __align__(16) __half g_oact[8388608];       // attention O [8192,1024] fp16
__device__ __align__(16) __half g_w3[4194304];         // W slots [4][1024,1024] (q,k,v,o)
__device__ __align__(16) __half g_q16[8388608];        // [bh][t][d]
__device__ __align__(16) __half g_k16[8388608];        // [bh][t][d]
__device__ __align__(16) __half g_v16t[8388608];       // [bh][d][t]

// ---------------- PTX helpers ------------------------------------------------
__device__ __forceinline__ uint32_t smem_u32(const void* p) {
    uint32_t a;
    asm("{ .reg .u64 t; cvta.to.shared.u64 t, %1; cvt.u32.u64 %0, t; }"
        : "=r"(a) : "l"(p));
    return a;
}

#define CP_ASYNC16(dst, src) \
    asm volatile("cp.async.cg.shared.global [%0], [%1], 16;" :: "r"(dst), "l"(src))
#define CP_COMMIT() asm volatile("cp.async.commit_group;" ::: "memory")
#define CP_WAIT1()  asm volatile("cp.async.wait_group 1;" ::: "memory")
#define CP_WAIT0()  asm volatile("cp.async.wait_group 0;" ::: "memory")

#define LDSM_X4(r0, r1, r2, r3, addr) \
    asm volatile("ldmatrix.sync.aligned.m8n8.x4.shared.b16 {%0,%1,%2,%3}, [%4];" \
        : "=r"(r0), "=r"(r1), "=r"(r2), "=r"(r3) : "r"(addr))

#define MMA16816(d, a0, a1, a2, a3, b0, b1) \
    asm volatile("mma.sync.aligned.m16n8k16.row.col.f32.f16.f16.f32 " \
        "{%0,%1,%2,%3},{%4,%5,%6,%7},{%8,%9},{%0,%1,%2,%3};" \
        : "+f"((d)[0]), "+f"((d)[1]), "+f"((d)[2]), "+f"((d)[3]) \
        : "r"(a0), "r"(a1), "r"(a2), "r"(a3), "r"(b0), "r"(b1))

__device__ __forceinline__ uint32_t pack_h2(float a, float b) {
    __half2 h = __float22half2_rn(make_float2(a, b));
    return *reinterpret_cast<uint32_t*>(&h);
}

// convert 8 floats (2x float4) -> 4 half2 words and STS 16B
__device__ __forceinline__ void sts_cvt8(uint32_t addr, float4 a, float4 b) {
    uint32_t r0 = pack_h2(a.x, a.y);
    uint32_t r1 = pack_h2(a.z, a.w);
    uint32_t r2 = pack_h2(b.x, b.y);
    uint32_t r3 = pack_h2(b.z, b.w);
    asm volatile("st.shared.v4.b32 [%0], {%1,%2,%3,%4};"
        :: "r"(addr), "r"(r0), "r"(r1), "r"(r2), "r"(r3) : "memory");
}

// ---------------- kernel 1: prep (weights fp16 + bias), 4224 blocks ---------
__global__ void __launch_bounds__(256)
prep_kernel(const float* __restrict__ Wq, const float* __restrict__ Wk,
            const float* __restrict__ Wv, const float* __restrict__ Wo,
            const float* __restrict__ table, const float* __restrict__ offset,
            __half* __restrict__ w3, float* __restrict__ biasOut)
{
    int blk = blockIdx.x;
    if (blk < 4096) {
        int wslot = blk >> 10;
        const float* src = (wslot == 0) ? Wq : (wslot == 1) ? Wk
                         : (wslot == 2) ? Wv : Wo;
        __half* dst = w3 + (size_t)wslot * 1048576;
        size_t off = ((size_t)(blk & 1023) * 256 + threadIdx.x) * 4;
        float4 x = *(const float4*)&src[off];
        __half2 p0 = __float22half2_rn(make_float2(x.x, x.y));
        __half2 p1 = __float22half2_rn(make_float2(x.z, x.w));
        __half2* d = (__half2*)&dst[off];
        d[0] = p0; d[1] = p1;
    } else {
        int idx = (blk - 4096) * 256 + threadIdx.x;
        if (idx < NREL * NH) {
            int r = idx / NH, h = idx % NH;
            float bounded = tanhf(offset[0]) * 0.5f;
            float adj = fminf(fmaxf((float)r + bounded, 0.0f), 2046.0f);
            float lof = floorf(adj);
            int lo = (int)lof;
            int hi = (int)ceilf(adj);
            float w = adj - lof;
            biasOut[h * NREL + r] =
                table[lo * NH + h] * (1.0f - w) + table[hi * NH + h] * w;
        }
    }
}

// ---------------- kernel 2a: Q/K/V projection, fp32 A + fused convert -------
// A fp32 [8192,1024], W fp16 [1024,1024]; CTA 128x128, 4 warps (2x2 of 64x64).
// modes: 1 -> fp16 [bh][t][d], 2 -> fp16 [bh][d][t]
#define ST_A   18432
#define ST_SZ  36864
#define KCHQ   16
__global__ void __launch_bounds__(128, 2)
gemm_qkv(const float* __restrict__ q, const float* __restrict__ k,
         const float* __restrict__ v, const __half* __restrict__ Wall,
         const float* __restrict__ bqv, const float* __restrict__ bkv,
         const float* __restrict__ bvv,
         __half* __restrict__ q16, __half* __restrict__ k16,
         __half* __restrict__ v16t)
{
    extern __shared__ __align__(128) char smem[];
    uint32_t sbase = smem_u32(smem);

    int z = blockIdx.z;
    const float* gAf = (z == 0) ? q : (z == 1) ? k : v;
    const __half* gB = Wall + (size_t)z * 1048576;
    const float* bias = (z == 0) ? bqv : (z == 1) ? bkv : bvv;
    __half* outH = (z == 0) ? q16 : (z == 1) ? k16 : v16t;
    int mode = (z < 2) ? 1 : 2;

    int tid = threadIdx.x;
    int wid = tid >> 5, lid = tid & 31;
    int wm = wid >> 1, wn = wid & 1;
    size_t bm = (size_t)blockIdx.y * 128;
    size_t bn = (size_t)blockIdx.x * 128;

    gAf += bm * 1024;
    gB  += bn * 1024;

    int ldrow = tid >> 3;          // 0..15
    int ldch  = tid & 7;

    // prologue: stages 0,1 (A: LDG fp32 + convert + STS; B: cp.async)
    #pragma unroll
    for (int s = 0; s < NSTG - 1; s++) {
        uint32_t st = sbase + s * ST_SZ;
        #pragma unroll
        for (int i = 0; i < 8; i++) {
            int row = ldrow + i * 16;
            const float* src = gAf + (size_t)row * 1024 + s * 64 + ldch * 8;
            float4 a0 = *(const float4*)src;
            float4 a1 = *(const float4*)(src + 4);
            sts_cvt8(st + row * 144 + ldch * 16, a0, a1);
            CP_ASYNC16(st + ST_A + row * 144 + ldch * 16,
                       gB + (size_t)row * 1024 + s * 64 + ldch * 8);
        }
        CP_COMMIT();
    }

    float acc[4][8][4];
    #pragma unroll
    for (int mi = 0; mi < 4; mi++)
        #pragma unroll
        for (int ni = 0; ni < 8; ni++)
            #pragma unroll
            for (int e = 0; e < 4; e++) acc[mi][ni][e] = 0.0f;

    uint32_t aOff = (uint32_t)((wm * 64 + (lid & 15)) * 144 + (lid >> 4) * 16);
    uint32_t bOff = (uint32_t)(ST_A +
        (wn * 64 + (lid & 7) + ((lid >> 4) << 3)) * 144 + ((lid >> 3) & 1) * 16);

    int cs = 0, ls = NSTG - 1;
    for (int c = 0; c < KCHQ; c++) {
        CP_WAIT1();
        __syncthreads();

        // stage c+2: issue A LDGs (held in regs), B cp.async now; STS after MMA
        float4 af[16];
        bool pf = (c + NSTG - 1 < KCHQ);
        int cc = c + NSTG - 1;
        uint32_t st2 = sbase + ls * ST_SZ;
        if (pf) {
            #pragma unroll
            for (int i = 0; i < 8; i++) {
                int row = ldrow + i * 16;
                const float* src = gAf + (size_t)row * 1024 + cc * 64 + ldch * 8;
                af[i * 2]     = *(const float4*)src;
                af[i * 2 + 1] = *(const float4*)(src + 4);
                CP_ASYNC16(st2 + ST_A + row * 144 + ldch * 16,
                           gB + (size_t)row * 1024 + cc * 64 + ldch * 8);
            }
        }
        CP_COMMIT();

        // compute stage c
        uint32_t st = sbase + cs * ST_SZ;
        #pragma unroll
        for (int kk = 0; kk < 4; kk++) {
            uint32_t a[4][4], b[4][4];
            #pragma unroll
            for (int mi = 0; mi < 4; mi++)
                LDSM_X4(a[mi][0], a[mi][1], a[mi][2], a[mi][3],
                        st + aOff + mi * (16 * 144) + kk * 32);
            #pragma unroll
            for (int nb = 0; nb < 4; nb++)
                LDSM_X4(b[nb][0], b[nb][1], b[nb][2], b[nb][3],
                        st + bOff + nb * (16 * 144) + kk * 32);
            #pragma unroll
            for (int mi = 0; mi < 4; mi++)
                #pragma unroll
                for (int nb = 0; nb < 4; nb++) {
                    MMA16816(acc[mi][nb * 2],
                             a[mi][0], a[mi][1], a[mi][2], a[mi][3],
                             b[nb][0], b[nb][1]);
                    MMA16816(acc[mi][nb * 2 + 1],
                             a[mi][0], a[mi][1], a[mi][2], a[mi][3],
                             b[nb][2], b[nb][3]);
                }
        }

        // convert + STS A for stage c+2 (after compute; visible after next sync)
        if (pf) {
            #pragma unroll
            for (int i = 0; i < 8; i++) {
                int row = ldrow + i * 16;
                sts_cvt8(st2 + row * 144 + ldch * 16, af[i * 2], af[i * 2 + 1]);
            }
        }

        cs = (cs == NSTG - 1) ? 0 : cs + 1;
        ls = (ls == NSTG - 1) ? 0 : ls + 1;
    }

    // epilogue
    #pragma unroll
    for (int mi = 0; mi < 4; mi++) {
        size_t r0 = bm + wm * 64 + mi * 16 + (lid >> 2);
        #pragma unroll
        for (int ni = 0; ni < 8; ni++) {
            size_t col = bn + wn * 64 + ni * 8 + (lid & 3) * 2;
            float2 bv = *(const float2*)&bias[col];
            float v00 = acc[mi][ni][0] + bv.x, v01 = acc[mi][ni][1] + bv.y;
            float v10 = acc[mi][ni][2] + bv.x, v11 = acc[mi][ni][3] + bv.y;
            if (mode == 1) {
                int h = (int)(col >> 6), d = (int)(col & 63);
                size_t b0 = r0 >> 10, t0 = r0 & 1023;
                __half2* d0 = (__half2*)&outH[(((b0 * NH + h) * T_SEQ + t0) * HD + d)];
                *d0 = __float22half2_rn(make_float2(v00, v01));
                size_t r1 = r0 + 8;
                __half2* d1 = (__half2*)&outH[(((r1 >> 10) * NH + h) * T_SEQ + (r1 & 1023)) * HD + d];
                *d1 = __float22half2_rn(make_float2(v10, v11));
            } else {
                int h = (int)(col >> 6), d = (int)(col & 63);
                size_t b0 = r0 >> 10, t0 = r0 & 1023;
                size_t base = ((b0 * NH + h) * HD + d) * T_SEQ;
                outH[base + t0] = __float2half_rn(v00);
                outH[base + T_SEQ + t0] = __float2half_rn(v01);
                outH[base + t0 + 8] = __float2half_rn(v10);
                outH[base + T_SEQ + t0 + 8] = __float2half_rn(v11);
            }
        }
    }
}

// ---------------- kernel 2b: output projection, fp16 A, K=1024 --------------
__global__ void __launch_bounds__(128, 2)
gemm_out(const __half* __restrict__ A, const __half* __restrict__ W,
         const float* __restrict__ bias, float* __restrict__ outF)
{
    extern __shared__ __align__(128) char smem[];
    uint32_t sbase = smem_u32(smem);

    int tid = threadIdx.x;
    int wid = tid >> 5, lid = tid & 31;
    int wm = wid >> 1, wn = wid & 1;
    size_t bm = (size_t)blockIdx.y * 128;
    size_t bn = (size_t)blockIdx.x * 128;

    const __half* gA = A + bm * 1024;
    const __half* gB = W + bn * 1024;

    int ldrow = tid >> 3;
    int ldch  = tid & 7;

    #pragma unroll
    for (int s = 0; s < NSTG - 1; s++) {
        uint32_t st = sbase + s * ST_SZ;
        #pragma unroll
        for (int i = 0; i < 8; i++) {
            int row = ldrow + i * 16;
            CP_ASYNC16(st + row * 144 + ldch * 16,
                       gA + (size_t)row * 1024 + s * 64 + ldch * 8);
            CP_ASYNC16(st + ST_A + row * 144 + ldch * 16,
                       gB + (size_t)row * 1024 + s * 64 + ldch * 8);
        }
        CP_COMMIT();
    }

    float acc[4][8][4];
    #pragma unroll
    for (int mi = 0; mi < 4; mi++)
        #pragma unroll
        for (int ni = 0; ni < 8; ni++)
            #pragma unroll
            for (int e = 0; e < 4; e++) acc[mi][ni][e] = 0.0f;

    uint32_t aOff = (uint32_t)((wm * 64 + (lid & 15)) * 144 + (lid >> 4) * 16);
    uint32_t bOff = (uint32_t)(ST_A +
        (wn * 64 + (lid & 7) + ((lid >> 4) << 3)) * 144 + ((lid >> 3) & 1) * 16);

    int cs = 0, ls = NSTG - 1;
    for (int c = 0; c < KCHQ; c++) {
        CP_WAIT1();
        __syncthreads();

        if (c + NSTG - 1 < KCHQ) {
            int cc = c + NSTG - 1;
            uint32_t st = sbase + ls * ST_SZ;
            #pragma unroll
            for (int i = 0; i < 8; i++) {
                int row = ldrow + i * 16;
                CP_ASYNC16(st + row * 144 + ldch * 16,
                           gA + (size_t)row * 1024 + cc * 64 + ldch * 8);
                CP_ASYNC16(st + ST_A + row * 144 + ldch * 16,
                           gB + (size_t)row * 1024 + cc * 64 + ldch * 8);
            }
        }
        CP_COMMIT();

        uint32_t st = sbase + cs * ST_SZ;
        #pragma unroll
        for (int kk = 0; kk < 4; kk++) {
            uint32_t a[4][4], b[4][4];
            #pragma unroll
            for (int mi = 0; mi < 4; mi++)
                LDSM_X4(a[mi][0], a[mi][1], a[mi][2], a[mi][3],
                        st + aOff + mi * (16 * 144) + kk * 32);
            #pragma unroll
            for (int nb = 0; nb < 4; nb++)
                LDSM_X4(b[nb][0], b[nb][1], b[nb][2], b[nb][3],
                        st + bOff + nb * (16 * 144) + kk * 32);
            #pragma unroll
            for (int mi = 0; mi < 4; mi++)
                #pragma unroll
                for (int nb = 0; nb < 4; nb++) {
                    MMA16816(acc[mi][nb * 2],
                             a[mi][0], a[mi][1], a[mi][2], a[mi][3],
                             b[nb][0], b[nb][1]);
                    MMA16816(acc[mi][nb * 2 + 1],
                             a[mi][0], a[mi][1], a[mi][2], a[mi][3],
                             b[nb][2], b[nb][3]);
                }
        }
        cs = (cs == NSTG - 1) ? 0 : cs + 1;
        ls = (ls == NSTG - 1) ? 0 : ls + 1;
    }

    #pragma unroll
    for (int mi = 0; mi < 4; mi++) {
        size_t r0 = bm + wm * 64 + mi * 16 + (lid >> 2);
        #pragma unroll
        for (int ni = 0; ni < 8; ni++) {
            size_t col = bn + wn * 64 + ni * 8 + (lid & 3) * 2;
            float2 bv = *(const float2*)&bias[col];
            *(float2*)&outF[r0 * 1024 + col] =
                make_float2(acc[mi][ni][0] + bv.x, acc[mi][ni][1] + bv.y);
            *(float2*)&outF[(r0 + 8) * 1024 + col] =
                make_float2(acc[mi][ni][2] + bv.x, acc[mi][ni][3] + bv.y);
        }
    }
}

// ---------------- kernel 3: fp16 mma flash attention -------------------------
#define A_SQ   0
#define A_SK   18432
#define A_SV   36864
#define A_SB   55296
#define A_SMEM 59904
__global__ void __launch_bounds__(256)
attn_mma(const __half* __restrict__ Q16, const __half* __restrict__ K16,
         const __half* __restrict__ V16t, const float* __restrict__ biasT,
         __half* __restrict__ Oh)
{
    extern __shared__ __align__(128) char smem[];
    uint32_t sbase = smem_u32(smem);
    float* sbias = (float*)(smem + A_SB);

    int bh = blockIdx.y;
    int h = bh & (NH - 1), b = bh >> 4;
    int q0 = blockIdx.x * 128;
    int tid = threadIdx.x;
    int w = tid >> 5, lid = tid & 31;

    const __half* gQ = Q16 + ((size_t)bh * T_SEQ + q0) * HD;
    const __half* gK = K16 + (size_t)bh * T_SEQ * HD;
    const __half* gV = V16t + (size_t)bh * HD * T_SEQ;

    {
        #pragma unroll
        for (int i = 0; i < 4; i++) {
            int id = tid + i * 256;
            int row = id >> 3, ch = id & 7;
            CP_ASYNC16(sbase + A_SQ + row * 144 + ch * 16,
                       gQ + (size_t)row * HD + ch * 8);
        }
        #pragma unroll
        for (int i = 0; i < 2; i++) {
            int id = tid + i * 256;
            int row = id >> 3, ch = id & 7;
            CP_ASYNC16(sbase + A_SK + row * 144 + ch * 16,
                       gK + (size_t)row * HD + ch * 8);
            CP_ASYNC16(sbase + A_SV + row * 144 + ch * 16,
                       gV + (size_t)row * T_SEQ + ch * 8);
        }
        CP_COMMIT();
    }
    for (int j = tid; j < 1151; j += 256)
        sbias[j] = biasT[h * NREL + q0 + j];

    float o[8][4];
    #pragma unroll
    for (int i = 0; i < 8; i++)
        #pragma unroll
        for (int e = 0; e < 4; e++) o[i][e] = 0.0f;
    float m0 = -1e30f, m1 = -1e30f, l0 = 0.0f, l1 = 0.0f;
    uint32_t qa[4][4];

    int r0loc = w * 16 + (lid >> 2);

    for (int it = 0; it < 16; it++) {
        CP_WAIT0();
        __syncthreads();

        if (it < 15) {
            int kt2 = (it + 1) * 64;
            uint32_t bo = ((it + 1) & 1) * 9216;
            #pragma unroll
            for (int i = 0; i < 2; i++) {
                int id = tid + i * 256;
                int row = id >> 3, ch = id & 7;
                CP_ASYNC16(sbase + A_SK + bo + row * 144 + ch * 16,
                           gK + (size_t)(kt2 + row) * HD + ch * 8);
                CP_ASYNC16(sbase + A_SV + bo + row * 144 + ch * 16,
                           gV + (size_t)row * T_SEQ + kt2 + ch * 8);
            }
        }
        CP_COMMIT();

        if (it == 0) {
            #pragma unroll
            for (int kk = 0; kk < 4; kk++)
                LDSM_X4(qa[kk][0], qa[kk][1], qa[kk][2], qa[kk][3],
                        sbase + A_SQ + (w * 16 + (lid & 15)) * 144
                        + (lid >> 4) * 16 + kk * 32);
        }

        uint32_t kb = sbase + A_SK + (it & 1) * 9216;
        uint32_t vb = sbase + A_SV + (it & 1) * 9216;

        float s[8][4];
        #pragma unroll
        for (int i = 0; i < 8; i++)
            #pragma unroll
            for (int e = 0; e < 4; e++) s[i][e] = 0.0f;
        #pragma unroll
        for (int kk = 0; kk < 4; kk++) {
            #pragma unroll
            for (int nb = 0; nb < 4; nb++) {
                uint32_t bb[4];
                LDSM_X4(bb[0], bb[1], bb[2], bb[3],
                        kb + (nb * 16 + (lid & 7) + ((lid >> 4) << 3)) * 144
                        + ((lid >> 3) & 1) * 16 + kk * 32);
                MMA16816(s[nb * 2], qa[kk][0], qa[kk][1], qa[kk][2], qa[kk][3],
                         bb[0], bb[1]);
                MMA16816(s[nb * 2 + 1], qa[kk][0], qa[kk][1], qa[kk][2], qa[kk][3],
                         bb[2], bb[3]);
            }
        }

        int kcol = it * 64 + (lid & 3) * 2;
        #pragma unroll
        for (int nt = 0; nt < 8; nt++) {
            int jb = r0loc + 1023 - (kcol + nt * 8);
            s[nt][0] = s[nt][0] * 0.125f + sbias[jb];
            s[nt][1] = s[nt][1] * 0.125f + sbias[jb - 1];
            s[nt][2] = s[nt][2] * 0.125f + sbias[jb + 8];
            s[nt][3] = s[nt][3] * 0.125f + sbias[jb + 7];
        }

        float mx0 = -1e30f, mx1 = -1e30f;
        #pragma unroll
        for (int nt = 0; nt < 8; nt++) {
            mx0 = fmaxf(mx0, fmaxf(s[nt][0], s[nt][1]));
            mx1 = fmaxf(mx1, fmaxf(s[nt][2], s[nt][3]));
        }
        mx0 = fmaxf(mx0, __shfl_xor_sync(0xffffffffu, mx0, 1, 4));
        mx0 = fmaxf(mx0, __shfl_xor_sync(0xffffffffu, mx0, 2, 4));
        mx1 = fmaxf(mx1, __shfl_xor_sync(0xffffffffu, mx1, 1, 4));
        mx1 = fmaxf(mx1, __shfl_xor_sync(0xffffffffu, mx1, 2, 4));
        float mn0 = fmaxf(m0, mx0), mn1 = fmaxf(m1, mx1);
        float c0 = __expf(m0 - mn0), c1 = __expf(m1 - mn1);
        m0 = mn0; m1 = mn1;
        float ls0 = 0.0f, ls1 = 0.0f;
        #pragma unroll
        for (int nt = 0; nt < 8; nt++) {
            s[nt][0] = __expf(s[nt][0] - mn0); ls0 += s[nt][0];
            s[nt][1] = __expf(s[nt][1] - mn0); ls0 += s[nt][1];
            s[nt][2] = __expf(s[nt][2] - mn1); ls1 += s[nt][2];
            s[nt][3] = __expf(s[nt][3] - mn1); ls1 += s[nt][3];
        }
        l0 = l0 * c0 + ls0;
        l1 = l1 * c1 + ls1;
        #pragma unroll
        for (int dn = 0; dn < 8; dn++) {
            o[dn][0] *= c0; o[dn][1] *= c0;
            o[dn][2] *= c1; o[dn][3] *= c1;
        }

        uint32_t ap[4][4];
        #pragma unroll
        for (int kk = 0; kk < 4; kk++) {
            ap[kk][0] = pack_h2(s[2 * kk][0], s[2 * kk][1]);
            ap[kk][1] = pack_h2(s[2 * kk][2], s[2 * kk][3]);
            ap[kk][2] = pack_h2(s[2 * kk + 1][0], s[2 * kk + 1][1]);
            ap[kk][3] = pack_h2(s[2 * kk + 1][2], s[2 * kk + 1][3]);
        }

        #pragma unroll
        for (int kk = 0; kk < 4; kk++) {
            #pragma unroll
            for (int db = 0; db < 4; db++) {
                uint32_t bb[4];
                LDSM_X4(bb[0], bb[1], bb[2], bb[3],
                        vb + (db * 16 + (lid & 7) + ((lid >> 4) << 3)) * 144
                        + ((lid >> 3) & 1) * 16 + kk * 32);
                MMA16816(o[db * 2], ap[kk][0], ap[kk][1], ap[kk][2], ap[kk][3],
                         bb[0], bb[1]);
                MMA16816(o[db * 2 + 1], ap[kk][0], ap[kk][1], ap[kk][2], ap[kk][3],
                         bb[2], bb[3]);
            }
        }
    }

    // epilogue -> fp16 O [8192][1024]
    l0 += __shfl_xor_sync(0xffffffffu, l0, 1, 4);
    l0 += __shfl_xor_sync(0xffffffffu, l0, 2, 4);
    l1 += __shfl_xor_sync(0xffffffffu, l1, 1, 4);
    l1 += __shfl_xor_sync(0xffffffffu, l1, 2, 4);
    float inv0 = 1.0f / l0, inv1 = 1.0f / l1;
    size_t row0 = (size_t)b * T_SEQ + q0 + r0loc;
    #pragma unroll
    for (int idx = 0; idx < 8; idx++) {
        int d = (idx >> 1) * 16 + (idx & 1) * 8 + (lid & 3) * 2;
        int col = h * HD + d;
        *(__half2*)&Oh[row0 * 1024 + col] =
            __float22half2_rn(make_float2(o[idx][0] * inv0, o[idx][1] * inv0));
        *(__half2*)&Oh[(row0 + 8) * 1024 + col] =
            __float22half2_rn(make_float2(o[idx][2] * inv1, o[idx][3] * inv1));
    }
}

// ---------------- launch -----------------------------------------------------
extern "C" void kernel_launch(void* const* d_in, const int* in_sizes, int n_in,
                              void* d_out, int out_size) {
    const float* query = (const float*)d_in[0];
    const float* key_  = (const float*)d_in[1];
    const float* value = (const float*)d_in[2];
    const float* Wq = (const float*)d_in[3];
    const float* bq = (const float*)d_in[4];
    const float* Wk = (const float*)d_in[5];
    const float* bk = (const float*)d_in[6];
    const float* Wv = (const float*)d_in[7];
    const float* bv = (const float*)d_in[8];
    const float* Wo = (const float*)d_in[9];
    const float* bo = (const float*)d_in[10];
    const float* bias_table = (const float*)d_in[11];
    const float* offset     = (const float*)d_in[12];
    float* out = (float*)d_out;

    void *pb, *po, *pw3, *pq16, *pk16, *pv16t;
    cudaGetSymbolAddress(&pb, g_bias);
    cudaGetSymbolAddress(&po, g_oact);
    cudaGetSymbolAddress(&pw3, g_w3);
    cudaGetSymbolAddress(&pq16, g_q16);
    cudaGetSymbolAddress(&pk16, g_k16);
    cudaGetSymbolAddress(&pv16t, g_v16t);
    __half* w3 = (__half*)pw3;
    __half* oact = (__half*)po;

    const int GEMM_SMEM = NSTG * ST_SZ;      // 110592
    cudaFuncSetAttribute(gemm_qkv, cudaFuncAttributeMaxDynamicSharedMemorySize, GEMM_SMEM);
    cudaFuncSetAttribute(gemm_out, cudaFuncAttributeMaxDynamicSharedMemorySize, GEMM_SMEM);
    cudaFuncSetAttribute(attn_mma, cudaFuncAttributeMaxDynamicSharedMemorySize, A_SMEM);

    // prep: weight fp16 converts + bias interpolation only
    prep_kernel<<<4224, 256>>>(Wq, Wk, Wv, Wo, bias_table, offset,
                               w3, (float*)pb);

    // Q/K/V projection: fp32 activations read directly, fused convert
    gemm_qkv<<<dim3(8, 64, 3), 128, GEMM_SMEM>>>(
        query, key_, value, w3, bq, bk, bv,
        (__half*)pq16, (__half*)pk16, (__half*)pv16t);

    // attention -> fp16 O
    attn_mma<<<dim3(8, 128), 256, A_SMEM>>>(
        (const __half*)pq16, (const __half*)pk16, (const __half*)pv16t,
        (const float*)pb, oact);

    // output projection: O * Wo, K = 1024
    gemm_out<<<dim3(8, 64), 128, GEMM_SMEM>>>(oact, w3 + 3145728, bo, out);
}